// round 17
// baseline (speedup 1.0000x reference)
#include <cuda_runtime.h>
#include <math.h>

#define CAP 32768
#define NB  32
#define CD  64
#define TOPK 16
#define NCHUNK 2048
#define FULLM 0xFFFFFFFFu
#define PITCHF 132      // tile row pitch: 132 floats = 66 ull pairs = 528 B
#define PITCHP 66

typedef unsigned long long ull;

#define FMA2(d, a, b, c) \
    asm("fma.rn.f32x2 %0, %1, %2, %3;" : "=l"(d) : "l"(a), "l"(b), "l"(c))
#define ADD2(d, a, b) \
    asm("add.rn.f32x2 %0, %1, %2;" : "=l"(d) : "l"(a), "l"(b))
#define PACK2(d, lo, hi) \
    asm("mov.b64 %0, {%1, %2};" : "=l"(d) : "f"(lo), "f"(hi))
#define UNPACK2(lo, hi, x) \
    asm("mov.b64 {%0, %1}, %2;" : "=f"(lo), "=f"(hi) : "l"(x))

// ---------------- scratch ----------------
__device__ float g_qpart[NB * CD];
__device__ float g_qn[NB * CD];
__device__ float g_s1qp[NB];
__device__ float g_scores[NB * CAP];
__device__ float g_cmax[NB * NCHUNK];

__device__ __forceinline__ unsigned ordf(float f) {
    unsigned u = __float_as_uint(f);
    return u ^ ((unsigned)((int)u >> 31) | 0x80000000u);
}
__device__ __forceinline__ float unordf(unsigned k) {
    unsigned u = (k & 0x80000000u) ? (k ^ 0x80000000u) : ~k;
    return __uint_as_float(u);
}

// ---------------- K0: query prep + s1qp (R15/R16, passed) ----------------
__global__ __launch_bounds__(256) void k0_prep(
    const float* __restrict__ qc, const float* __restrict__ qctx,
    const float* __restrict__ W1, const float* __restrict__ b1,
    const float* __restrict__ W2)
{
    __shared__ float sq[64];
    __shared__ float sp[4][64];
    __shared__ float sps[2];
    __shared__ float sd[2];
    int b = blockIdx.x, tid = threadIdx.x;
    int h = tid & 63, part = tid >> 6;

    if (tid < 64) sq[tid] = qc[b * CD + tid];
    float v = (tid < 64) ? qctx[b * CD + tid] : 0.0f;
    __syncthreads();

    float s = 0.0f;
    #pragma unroll
    for (int j = 0; j < 16; j++) {
        int d = part * 16 + j;
        s = fmaf(sq[d], W1[d * CD + h], s);
    }
    sp[part][h] = s;

    float ss = v * v;
    #pragma unroll
    for (int o = 16; o; o >>= 1) ss += __shfl_xor_sync(FULLM, ss, o);
    if (tid == 0)  sps[0] = ss;
    if (tid == 32) sps[1] = ss;
    __syncthreads();

    if (tid < 64) {
        float qv = sp[0][tid] + sp[1][tid] + sp[2][tid] + sp[3][tid] + b1[tid];
        g_qpart[b * CD + tid] = qv;
        float inv = 1.0f / fmaxf(sqrtf(sps[0] + sps[1]), 1e-8f);
        g_qn[b * CD + tid] = v * inv;
        float c1 = qv * W2[tid];
        #pragma unroll
        for (int o = 16; o; o >>= 1) c1 += __shfl_xor_sync(FULLM, c1, o);
        if (tid == 0)  sd[0] = c1;
        if (tid == 32) sd[1] = c1;
    }
    __syncthreads();
    if (tid == 0) g_s1qp[b] = sd[0] + sd[1];
}

// ---------------- K2: packed GEMM (dup-A) + packed abs-trick scoring ----------------
// dynamic smem layout:
//   [0)      sB   : 64*64 floats (W1 bottom)            16384 B
//   [16384)  sAd  : 4 warps * 16 rows * 528 B           33792 B  (dup-A, then m_part)
//   [50176)  s_mx : 4*2*16 float4                        2048 B
//   [52224)  s_w2 : 16 float4                             256 B
//   [52480)  s_inv: 8 floats                               32 B
//   [52512)  s_s1m: 4*16 floats                           256 B
#define SMEM_K2 52768

__global__ __launch_bounds__(128) void k2_fused(
    const float* __restrict__ mc, const float* __restrict__ mctx,
    const float* __restrict__ fresh,
    const float* __restrict__ W1, const float* __restrict__ W2,
    const float* __restrict__ b2p)
{
    extern __shared__ char dyn[];
    float*  sB    = (float*)dyn;
    float*  sAdF  = (float*)(dyn + 16384);
    ull*    sAdP  = (ull*)(dyn + 16384);
    float4* s_mx  = (float4*)(dyn + 50176);
    float4* s_w2  = (float4*)(dyn + 52224);
    float*  s_inv = (float*)(dyn + 52480);
    float*  s_s1m = (float*)(dyn + 52512);

    int tid = threadIdx.x, w = tid >> 5, lane = tid & 31;
    float* sAw  = sAdF + w * (16 * PITCHF);
    ull*   sAwP = sAdP + w * (16 * PITCHP);

    {
        const float4* src = (const float4*)(W1 + 64 * 64);
        float4* dst = (float4*)sB;
        for (int i = tid; i < 1024; i += 128) dst[i] = src[i];
    }
    if (tid < 16) s_w2[tid] = ((const float4*)W2)[tid];
    __syncthreads();

    float b2v = b2p[0];
    float s1qp_lane = g_s1qp[lane];

    // per-lane query vectors as packed pairs (lane = query b)
    ull qp2[32], qn2[32];
    {
        const ulonglong2* a4 = (const ulonglong2*)(g_qpart + lane * CD);
        const ulonglong2* n4 = (const ulonglong2*)(g_qn + lane * CD);
        #pragma unroll
        for (int i = 0; i < 16; i++) {
            ulonglong2 a = a4[i];
            qp2[2 * i] = a.x; qp2[2 * i + 1] = a.y;
            ulonglong2 n = n4[i];
            qn2[2 * i] = n.x; qn2[2 * i + 1] = n.y;
        }
    }

    int rg = lane >> 3;          // GEMM: 4 rows per lane
    int hg = lane & 7;           // GEMM: 8 h-cols per lane (4 pairs)
    int half = lane >> 4, q = lane & 15;

    #pragma unroll 1
    for (int it = 0; it < 2; it++) {
        int chunk = blockIdx.x * 8 + w * 2 + it;
        int base = chunk * 16;

        __syncwarp();
        // ---- stage mc rows as DUPLICATED pairs: sAwP[r*66 + d] = (v, v) ----
        {
            const float4* mcp = (const float4*)(mc + (size_t)base * CD);
            #pragma unroll
            for (int j = 0; j < 8; j++) {
                int idx = lane + 32 * j;
                int r = idx >> 4, cc = idx & 15;
                float4 v = mcp[idx];
                ull p0, p1, p2, p3;
                PACK2(p0, v.x, v.x);
                PACK2(p1, v.y, v.y);
                PACK2(p2, v.z, v.z);
                PACK2(p3, v.w, v.w);
                ulonglong2 lo; lo.x = p0; lo.y = p1;
                ulonglong2 hi; hi.x = p2; hi.y = p3;
                *(ulonglong2*)&sAwP[r * PITCHP + cc * 4]     = lo;
                *(ulonglong2*)&sAwP[r * PITCHP + cc * 4 + 2] = hi;
            }
        }
        __syncwarp();

        // ---- GEMM packed over h: m_part[r][h] = sum_d mc[r][d]*W1b[d][h] ----
        ull acc[4][4];   // [r][hp], h = hg*8 + 2*hp + {0,1}
        #pragma unroll
        for (int r = 0; r < 4; r++)
            #pragma unroll
            for (int j = 0; j < 4; j++) acc[r][j] = 0ull;

        #pragma unroll 4
        for (int d2 = 0; d2 < 32; d2++) {     // 2 d's per iteration
            int d = 2 * d2;
            ulonglong2 a0 = *(const ulonglong2*)&sAwP[(rg * 4 + 0) * PITCHP + d];
            ulonglong2 a1 = *(const ulonglong2*)&sAwP[(rg * 4 + 1) * PITCHP + d];
            ulonglong2 a2 = *(const ulonglong2*)&sAwP[(rg * 4 + 2) * PITCHP + d];
            ulonglong2 a3 = *(const ulonglong2*)&sAwP[(rg * 4 + 3) * PITCHP + d];
            ulonglong2 b01a = *(const ulonglong2*)&sB[d * 64 + hg * 8];
            ulonglong2 b23a = *(const ulonglong2*)&sB[d * 64 + hg * 8 + 4];
            ulonglong2 b01b = *(const ulonglong2*)&sB[(d + 1) * 64 + hg * 8];
            ulonglong2 b23b = *(const ulonglong2*)&sB[(d + 1) * 64 + hg * 8 + 4];
            FMA2(acc[0][0], a0.x, b01a.x, acc[0][0]);
            FMA2(acc[0][1], a0.x, b01a.y, acc[0][1]);
            FMA2(acc[0][2], a0.x, b23a.x, acc[0][2]);
            FMA2(acc[0][3], a0.x, b23a.y, acc[0][3]);
            FMA2(acc[1][0], a1.x, b01a.x, acc[1][0]);
            FMA2(acc[1][1], a1.x, b01a.y, acc[1][1]);
            FMA2(acc[1][2], a1.x, b23a.x, acc[1][2]);
            FMA2(acc[1][3], a1.x, b23a.y, acc[1][3]);
            FMA2(acc[2][0], a2.x, b01a.x, acc[2][0]);
            FMA2(acc[2][1], a2.x, b01a.y, acc[2][1]);
            FMA2(acc[2][2], a2.x, b23a.x, acc[2][2]);
            FMA2(acc[2][3], a2.x, b23a.y, acc[2][3]);
            FMA2(acc[3][0], a3.x, b01a.x, acc[3][0]);
            FMA2(acc[3][1], a3.x, b01a.y, acc[3][1]);
            FMA2(acc[3][2], a3.x, b23a.x, acc[3][2]);
            FMA2(acc[3][3], a3.x, b23a.y, acc[3][3]);
            FMA2(acc[0][0], a0.y, b01b.x, acc[0][0]);
            FMA2(acc[0][1], a0.y, b01b.y, acc[0][1]);
            FMA2(acc[0][2], a0.y, b23b.x, acc[0][2]);
            FMA2(acc[0][3], a0.y, b23b.y, acc[0][3]);
            FMA2(acc[1][0], a1.y, b01b.x, acc[1][0]);
            FMA2(acc[1][1], a1.y, b01b.y, acc[1][1]);
            FMA2(acc[1][2], a1.y, b23b.x, acc[1][2]);
            FMA2(acc[1][3], a1.y, b23b.y, acc[1][3]);
            FMA2(acc[2][0], a2.y, b01b.x, acc[2][0]);
            FMA2(acc[2][1], a2.y, b01b.y, acc[2][1]);
            FMA2(acc[2][2], a2.y, b23b.x, acc[2][2]);
            FMA2(acc[2][3], a2.y, b23b.y, acc[2][3]);
            FMA2(acc[3][0], a3.y, b01b.x, acc[3][0]);
            FMA2(acc[3][1], a3.y, b01b.y, acc[3][1]);
            FMA2(acc[3][2], a3.y, b23b.x, acc[3][2]);
            FMA2(acc[3][3], a3.y, b23b.y, acc[3][3]);
        }
        __syncwarp();
        // write m_part (packed stores, float layout identical to R16) + s1m epilogue
        {
            ulonglong2 w2p0 = *(const ulonglong2*)&s_w2[hg * 2];       // w2 pairs h..h+3
            ulonglong2 w2p1 = *(const ulonglong2*)&s_w2[hg * 2 + 1];   // w2 pairs h+4..h+7
            #pragma unroll
            for (int r = 0; r < 4; r++) {
                ulonglong2 lo; lo.x = acc[r][0]; lo.y = acc[r][1];
                ulonglong2 hi; hi.x = acc[r][2]; hi.y = acc[r][3];
                *(ulonglong2*)&sAw[(rg * 4 + r) * PITCHF + hg * 8]     = lo;
                *(ulonglong2*)&sAw[(rg * 4 + r) * PITCHF + hg * 8 + 4] = hi;
                ull sp2 = 0ull;
                FMA2(sp2, acc[r][0], w2p0.x, sp2);
                FMA2(sp2, acc[r][1], w2p0.y, sp2);
                FMA2(sp2, acc[r][2], w2p1.x, sp2);
                FMA2(sp2, acc[r][3], w2p1.y, sp2);
                float spa, spb;
                UNPACK2(spa, spb, sp2);
                float sp = spa + spb;
                sp += __shfl_xor_sync(FULLM, sp, 1);
                sp += __shfl_xor_sync(FULLM, sp, 2);
                sp += __shfl_xor_sync(FULLM, sp, 4);
                if (hg == 0) s_s1m[w * 16 + rg * 4 + r] = sp;
            }
        }
        __syncwarp();

        // ---- scoring (R16 verbatim): packed f32x2 + and-abs; lane = query b ----
        float4 nmx = ((const float4*)(mctx + (size_t)(base + half) * CD))[q];
        float cmax = -1e30f;

        #pragma unroll 1
        for (int pp = 0; pp < 4; pp++) {
            float out4[4];
            #pragma unroll
            for (int p2 = 0; p2 < 2; p2++) {
                int p = 2 * pp + p2;
                int c0 = base + 2 * p;
                s_mx[(w * 2 + half) * 16 + q] = nmx;
                float ssn = nmx.x * nmx.x + nmx.y * nmx.y + nmx.z * nmx.z + nmx.w * nmx.w;
                ssn += __shfl_xor_sync(FULLM, ssn, 1);
                ssn += __shfl_xor_sync(FULLM, ssn, 2);
                ssn += __shfl_xor_sync(FULLM, ssn, 4);
                ssn += __shfl_xor_sync(FULLM, ssn, 8);
                if (q == 0) s_inv[w * 2 + half] = 1.0f / fmaxf(sqrtf(ssn), 1e-8f);
                __syncwarp();
                if (p < 7)
                    nmx = ((const float4*)(mctx + (size_t)(c0 + 2 + half) * CD))[q];
                #pragma unroll
                for (int r = 0; r < 2; r++) {
                    int c = c0 + r;
                    int rl = 2 * p + r;
                    ull ac01 = 0ull, ac23 = 0ull;
                    ull ax01 = 0ull, ax23 = 0ull;
                    #pragma unroll
                    for (int i = 0; i < 16; i++) {
                        ulonglong2 mp2 = *(const ulonglong2*)&sAw[rl * PITCHF + 4 * i];
                        ulonglong2 mx2 = *(const ulonglong2*)&s_mx[(w * 2 + r) * 16 + i];
                        ulonglong2 w22 = *(const ulonglong2*)&s_w2[i];
                        ull t01; ADD2(t01, qp2[2 * i], mp2.x);
                        ull t23; ADD2(t23, qp2[2 * i + 1], mp2.y);
                        ull a01 = t01 & 0x7FFFFFFF7FFFFFFFull;
                        ull a23 = t23 & 0x7FFFFFFF7FFFFFFFull;
                        FMA2(ac01, w22.x, a01, ac01);
                        FMA2(ac23, w22.y, a23, ac23);
                        FMA2(ax01, qn2[2 * i], mx2.x, ax01);
                        FMA2(ax23, qn2[2 * i + 1], mx2.y, ax23);
                    }
                    float s2a, s2b, s2c, s2d, xa, xb, xc, xd;
                    UNPACK2(s2a, s2b, ac01);
                    UNPACK2(s2c, s2d, ac23);
                    UNPACK2(xa, xb, ax01);
                    UNPACK2(xc, xd, ax23);
                    float S2 = (s2a + s2b) + (s2c + s2d);
                    float S1 = s1qp_lane + s_s1m[w * 16 + rl];
                    float z  = fmaf(0.5f, S1 + S2, b2v);
                    float ctx = ((xa + xb) + (xc + xd)) * s_inv[w * 2 + r];
                    float sig = 1.0f / (1.0f + __expf(-z));
                    float score = 0.5f * sig + 0.3f * ctx + 0.2f * fresh[c];
                    out4[2 * p2 + r] = score;
                    cmax = fmaxf(cmax, score);
                }
                __syncwarp();
            }
            *(float4*)&g_scores[(size_t)lane * CAP + base + 4 * pp] =
                make_float4(out4[0], out4[1], out4[2], out4[3]);
        }
        g_cmax[lane * NCHUNK + chunk] = cmax;
    }
}

// ---------------- K3: threshold-filter top-16 + gather ----------------
__global__ __launch_bounds__(256) void k3_topk(
    const float* __restrict__ mc, const float* __restrict__ fresh,
    float* __restrict__ out)
{
    __shared__ unsigned s_key[NCHUNK];
    __shared__ unsigned s_tm[256];
    __shared__ unsigned s_tau;
    __shared__ int s_cnt, s_cnt2;
    __shared__ int s_cand[64];
    __shared__ unsigned s_ekey[64];
    __shared__ int s_eidx[64];
    __shared__ int s_sel[TOPK];
    __shared__ float s_val[TOPK];

    int b = blockIdx.x;
    int tid = threadIdx.x;
    int lane = tid & 31;

    unsigned tmax = 0;
    #pragma unroll
    for (int j = 0; j < 8; j++) {
        unsigned k = ordf(g_cmax[b * NCHUNK + tid * 8 + j]);
        s_key[tid * 8 + j] = k;
        tmax = max(tmax, k);
    }
    s_tm[tid] = tmax;
    if (tid == 0) { s_cnt = 0; s_cnt2 = 0; }
    if (tid < 64) s_ekey[tid] = 0u;
    __syncthreads();

    if (tid < 32) {
        unsigned gm = 0;
        #pragma unroll
        for (int j = 0; j < 8; j++) gm = max(gm, s_tm[lane * 8 + j]);
        int rank = 0;
        #pragma unroll
        for (int j = 0; j < 32; j++) {
            unsigned vj = __shfl_sync(FULLM, gm, j);
            rank += (vj > gm) || (vj == gm && j < lane);
        }
        unsigned eq = __ballot_sync(FULLM, rank == 15);
        unsigned tau = __shfl_sync(FULLM, gm, __ffs(eq) - 1);
        if (lane == 0) s_tau = tau;
    }
    __syncthreads();
    unsigned tau = s_tau;

    #pragma unroll
    for (int j = 0; j < 8; j++) {
        int ch = tid * 8 + j;
        if (s_key[ch] >= tau) {
            int p = atomicAdd(&s_cnt, 1);
            if (p < 64) s_cand[p] = ch;
        }
    }
    __syncthreads();
    int cnt = min(s_cnt, 64);

    for (int i = tid; i < cnt * 16; i += 256) {
        int ch = s_cand[i >> 4];
        int gi = ch * 16 + (i & 15);
        unsigned key = ordf(g_scores[(size_t)b * CAP + gi]);
        if (key >= tau) {
            int p = atomicAdd(&s_cnt2, 1);
            if (p < 64) { s_ekey[p] = key; s_eidx[p] = gi; }
        }
    }
    __syncthreads();

    if (tid < 32) {
        for (int k = 0; k < TOPK; k++) {
            unsigned lkey = 0; int lidx = 0x7FFFFFFF; int lpos = -1;
            #pragma unroll
            for (int j = 0; j < 2; j++) {
                int p = lane + 32 * j;
                unsigned kk = s_ekey[p];
                int ii = s_eidx[p];
                if (kk > lkey || (kk == lkey && kk != 0u && ii < lidx)) {
                    lkey = kk; lidx = ii; lpos = p;
                }
            }
            unsigned m = __reduce_max_sync(FULLM, lkey);
            int cand = (lkey == m) ? lidx : 0x7FFFFFFF;
            int gi = __reduce_min_sync(FULLM, cand);
            if (lane == 0) { s_sel[k] = gi; s_val[k] = unordf(m); }
            if (lkey == m && lidx == gi) s_ekey[lpos] = 0u;
            __syncwarp();
        }
    }
    __syncthreads();

    for (int i = tid; i < TOPK * CD; i += 256) {
        int k = i >> 6, h = i & 63;
        out[(size_t)b * (TOPK * CD) + i] = mc[(size_t)s_sel[k] * CD + h];
    }
    if (tid < TOPK) {
        out[NB * TOPK * CD + b * TOPK + tid] = s_val[tid];
        out[NB * TOPK * CD + NB * TOPK + b * TOPK + tid] = fresh[s_sel[tid]];
    }
}

// ---------------- launch ----------------
extern "C" void kernel_launch(void* const* d_in, const int* in_sizes, int n_in,
                              void* d_out, int out_size)
{
    const float* qc    = (const float*)d_in[0];
    const float* qctx  = (const float*)d_in[1];
    const float* mc    = (const float*)d_in[2];
    const float* mctx  = (const float*)d_in[3];
    const float* fresh = (const float*)d_in[4];
    const float* W1    = (const float*)d_in[5];
    const float* b1    = (const float*)d_in[6];
    const float* W2    = (const float*)d_in[7];
    const float* b2    = (const float*)d_in[8];
    float* out = (float*)d_out;

    cudaFuncSetAttribute(k2_fused, cudaFuncAttributeMaxDynamicSharedMemorySize, SMEM_K2);

    k0_prep<<<NB, 256>>>(qc, qctx, W1, b1, W2);
    k2_fused<<<NCHUNK / 8, 128, SMEM_K2>>>(mc, mctx, fresh, W1, W2, b2);
    k3_topk<<<NB, 256>>>(mc, fresh, out);
}